// round 6
// baseline (speedup 1.0000x reference)
#include <cuda_runtime.h>
#include <cstddef>

// Problem constants
#define Bx 8
#define Cc 64
#define Nn 512
#define Tt 288
#define Kk 32
#define TT 8            // t-tile per block
#define NTILE 32        // phase-B n-tile
#define HETS 520        // sHET row stride in floats (512 + 8 pad -> 8-way max on staging only)
#define YSTR 66         // sY c stride (floats)

typedef unsigned long long u64;

// smem layout (floats)
#define OFF_HE   0                        // [512][32]  HEs, k contiguous
#define OFF_HET  (OFF_HE + Nn * Kk)       // [32][520]  HEs transposed, n contiguous
#define OFF_EMT  (OFF_HET + Kk * HETS)    // [32][32]   edge_map transposed
#define OFF_Y    (OFF_EMT + Kk * Kk)      // [32*8][66] y bounce tile
#define SMEM_FLOATS (OFF_Y + NTILE * TT * YSTR)   // 50944 floats = 203776 B

// ---- packed f32x2 helpers (FFMA2 is PTX-only on sm_103a) ----
__device__ __forceinline__ u64 pack2(float x, float y) {
    u64 r; asm("mov.b64 %0, {%1, %2};" : "=l"(r) : "f"(x), "f"(y)); return r;
}
__device__ __forceinline__ float2 unpack2(u64 v) {
    float2 r; asm("mov.b64 {%0, %1}, %2;" : "=f"(r.x), "=f"(r.y) : "l"(v)); return r;
}
__device__ __forceinline__ u64 ffma2(u64 a, u64 b, u64 c) {
    u64 d; asm("fma.rn.f32x2 %0, %1, %2, %3;" : "=l"(d) : "l"(a), "l"(b), "l"(c)); return d;
}

extern __shared__ float smem[];

// ============================================================================
// Fully fused: stage1 (HF = HEs^T @ x), edge-map mix (HO), stage3 (scatter),
// residual + LayerNorm, all in one block per (b, t-tile of 8).
// Block = 512 threads: thread = (c, t); HO stays in the producing thread's
// registers between stages. grid = (36 t-tiles, 8 b).
// ============================================================================
__global__ void __launch_bounds__(512, 1)
fused_hgl(const float* __restrict__ x, const float* __restrict__ HEs,
          const float* __restrict__ em, float* __restrict__ out) {
    float* sHE  = smem + OFF_HE;
    float* sHET = smem + OFF_HET;
    float* sEMT = smem + OFF_EMT;
    float* sY   = smem + OFF_Y;

    const int tid   = threadIdx.x;
    const int ttile = blockIdx.x;
    const int b     = blockIdx.y;
    const int t0    = ttile * TT;
    const int c     = tid >> 3;          // 0..63
    const int t     = tid & 7;           // 0..7

    // ---- stage HEs (both layouts) + EM^T ----
    #pragma unroll
    for (int i = 0; i < 32; i++) {
        int flat = i * 512 + tid;        // flat = n*32 + k
        float v = HEs[flat];
        sHE[flat] = v;
        sHET[(flat & 31) * HETS + (flat >> 5)] = v;
    }
    #pragma unroll
    for (int i = 0; i < 2; i++) {
        int flat = i * 512 + tid;        // flat = k'*32 + j
        int kp = flat >> 5, k = flat & 31;
        sEMT[k * Kk + kp] = em[flat];    // sEMT[j][k'] = EM[k'][j]
    }
    __syncthreads();

    // =========================== Phase A: HF ================================
    // acc[kp] = (HF[2kp], HF[2kp+1]) for this (c, t)
    const float* xp = x + ((size_t)(b * Cc + c) * Nn) * Tt + t0 + t;

    u64 acc[16];
    #pragma unroll
    for (int i = 0; i < 16; i++) acc[i] = 0ull;

    float xv[8];
    #pragma unroll
    for (int i = 0; i < 8; i++) xv[i] = xp[i * Tt];

    #pragma unroll 1
    for (int n0 = 0; n0 < Nn; n0 += 8) {
        float xn[8];
        const bool more = (n0 + 8) < Nn;
        #pragma unroll
        for (int i = 0; i < 8; i++) xn[i] = more ? xp[(n0 + 8 + i) * Tt] : 0.f;

        #pragma unroll
        for (int i = 0; i < 8; i++) {
            u64 xb = pack2(xv[i], xv[i]);
            const ulonglong2* he4 = (const ulonglong2*)(sHE + (n0 + i) * Kk);
            #pragma unroll
            for (int q = 0; q < 8; q++) {            // broadcast LDS.128
                ulonglong2 hh = he4[q];
                acc[2 * q]     = ffma2(hh.x, xb, acc[2 * q]);
                acc[2 * q + 1] = ffma2(hh.y, xb, acc[2 * q + 1]);
            }
        }
        #pragma unroll
        for (int i = 0; i < 8; i++) xv[i] = xn[i];
    }

    // ---- edge-map mix: hm[k'] = sum_k EM[k',k] * HF[k] ----
    u64 hm[16];
    #pragma unroll
    for (int i = 0; i < 16; i++) hm[i] = 0ull;
    #pragma unroll
    for (int k = 0; k < Kk; k++) {
        float2 a = unpack2(acc[k >> 1]);
        float hf = (k & 1) ? a.y : a.x;
        u64 hb = pack2(hf, hf);
        const ulonglong2* emr = (const ulonglong2*)(sEMT + k * Kk);
        #pragma unroll
        for (int q = 0; q < 8; q++) {
            ulonglong2 ee = emr[q];
            hm[2 * q]     = ffma2(ee.x, hb, hm[2 * q]);
            hm[2 * q + 1] = ffma2(ee.y, hb, hm[2 * q + 1]);
        }
    }

    // ---- HO = relu(hm) + HF, duplicated per k for phase-B FFMA2 ----
    u64 hod[32];
    #pragma unroll
    for (int kp = 0; kp < 16; kp++) {
        float2 m = unpack2(hm[kp]);
        float2 f = unpack2(acc[kp]);
        float h0 = fmaxf(m.x, 0.f) + f.x;
        float h1 = fmaxf(m.y, 0.f) + f.y;
        hod[2 * kp]     = pack2(h0, h0);
        hod[2 * kp + 1] = pack2(h1, h1);
    }

    // =========================== Phase B ====================================
    // epilogue thread remap: (enl, et, ech); shfl partner = lane^1
    const int enl = tid >> 4;            // 0..31 local n
    const int et  = (tid >> 1) & 7;      // 0..7  t
    const int ech = tid & 1;             // c half
    const int cb  = ech * 32;
    const size_t cstride = (size_t)Nn * Tt;

    #pragma unroll 1
    for (int nt = 0; nt < 16; nt++) {
        const int n0 = nt * NTILE;

        // y[n-pair] accumulation for this (c, t): a2[j] = (y[n0+2j], y[n0+2j+1])
        u64 a2[16];
        #pragma unroll
        for (int j = 0; j < 16; j++) a2[j] = 0ull;

        #pragma unroll
        for (int k = 0; k < Kk; k++) {
            u64 hd = hod[k];
            const ulonglong2* hr = (const ulonglong2*)(sHET + k * HETS + n0);
            #pragma unroll
            for (int q = 0; q < 8; q++) {            // broadcast LDS.128: 4 n's
                ulonglong2 hh = hr[q];
                a2[2 * q]     = ffma2(hh.x, hd, a2[2 * q]);
                a2[2 * q + 1] = ffma2(hh.y, hd, a2[2 * q + 1]);
            }
        }

        // bounce y tile through smem: rows [nl][t][c]
        #pragma unroll
        for (int j = 0; j < 16; j++) {
            float2 y = unpack2(a2[j]);
            sY[((2 * j)     * TT + t) * YSTR + c] = y.x;
            sY[((2 * j + 1) * TT + t) * YSTR + c] = y.y;
        }
        __syncthreads();

        // ---- epilogue: relu + residual + LN over c (2 threads per (n,t)) ----
        const int n = n0 + enl;
        const float* yrow = sY + (enl * TT + et) * YSTR + cb;
        const size_t xbase = ((size_t)(b * Cc + cb) * Nn + n) * Tt + t0 + et;

        float z[32];
        float s1 = 0.f, s2 = 0.f;
        #pragma unroll
        for (int i = 0; i < 32; i++) {
            float zz = fmaxf(yrow[i], 0.f) + x[xbase + (size_t)i * cstride];
            z[i] = zz;
            s1 += zz;
            s2 += zz * zz;
        }
        s1 += __shfl_xor_sync(0xffffffffu, s1, 1);
        s2 += __shfl_xor_sync(0xffffffffu, s2, 1);
        float mu  = s1 * (1.f / 64.f);
        float var = fmaf(mu, -mu, s2 * (1.f / 64.f));
        float inv = rsqrtf(var + 1e-5f);
        #pragma unroll
        for (int i = 0; i < 32; i++)
            out[xbase + (size_t)i * cstride] = (z[i] - mu) * inv;
        __syncthreads();
    }
}

// ============================================================================
extern "C" void kernel_launch(void* const* d_in, const int* in_sizes, int n_in,
                              void* d_out, int out_size) {
    const float* x   = (const float*)d_in[0];
    const float* HEs = (const float*)d_in[1];
    const float* em  = (const float*)d_in[2];
    float* out = (float*)d_out;

    const int smem_bytes = SMEM_FLOATS * 4;   // 203776
    cudaFuncSetAttribute(fused_hgl, cudaFuncAttributeMaxDynamicSharedMemorySize, smem_bytes);

    fused_hgl<<<dim3(Tt / TT, Bx), 512, smem_bytes>>>(x, HEs, em, out);
}

// round 7
// speedup vs baseline: 1.1604x; 1.1604x over previous
#include <cuda_runtime.h>
#include <cstddef>

// Problem constants
#define Bx 8
#define Cc 64
#define Nn 512
#define Tt 288
#define Kk 32
#define TT 8            // t-tile per block
#define NTILE 16        // phase-B n-tile
#define YSTR 66         // sY c stride (floats)
#define CHN 8           // n's per cp.async chunk
#define NCH (Nn / CHN)  // 64 chunks
#define CHUNK_FLOATS (CHN * Cc * TT)   // 4096 floats = 16KB

typedef unsigned long long u64;

// smem layout (floats)
#define OFF_HE   0                          // [512][32] HEs, k contiguous
#define OFF_EMT  (OFF_HE + Nn * Kk)         // [32][32]  edge_map transposed
#define OFF_UN   (OFF_EMT + Kk * Kk)        // union: phase-A x ring (2*4096) / phase-B y tile (16*8*66=8448)
#define UN_FLOATS 8448
#define SMEM_FLOATS (OFF_UN + UN_FLOATS)    // 25856 floats = 103424 B  -> 2 CTAs/SM

// ---- packed f32x2 helpers (FFMA2 is PTX-only on sm_103a) ----
__device__ __forceinline__ u64 pack2(float x, float y) {
    u64 r; asm("mov.b64 %0, {%1, %2};" : "=l"(r) : "f"(x), "f"(y)); return r;
}
__device__ __forceinline__ float2 unpack2(u64 v) {
    float2 r; asm("mov.b64 {%0, %1}, %2;" : "=f"(r.x), "=f"(r.y) : "l"(v)); return r;
}
__device__ __forceinline__ u64 ffma2(u64 a, u64 b, u64 c) {
    u64 d; asm("fma.rn.f32x2 %0, %1, %2, %3;" : "=l"(d) : "l"(a), "l"(b), "l"(c)); return d;
}
__device__ __forceinline__ unsigned smem_u32(const void* p) {
    unsigned a;
    asm("{ .reg .u64 t; cvta.to.shared.u64 t, %1; cvt.u32.u64 %0, t; }" : "=r"(a) : "l"(p));
    return a;
}
__device__ __forceinline__ void cp_async16(unsigned dst, const void* src) {
    asm volatile("cp.async.cg.shared.global [%0], [%1], 16;" :: "r"(dst), "l"(src) : "memory");
}

extern __shared__ float smem[];

// ============================================================================
// Fully fused, latency-tolerant version.
// Block = 256 threads = (cl 0..31, t 0..7); each thread owns c = cl and cl+32.
// grid = (36 t-tiles, 8 b) = 288 blocks; 2 CTAs/SM -> single wave.
// Phase A: HF via cp.async-ring staged x (no LDG latency exposure).
// Phase B: scatter via k-pair FFMA2 dot + horizontal add (no hod duplication).
// ============================================================================
__global__ void __launch_bounds__(256, 2)
fused_hgl(const float* __restrict__ x, const float* __restrict__ HEs,
          const float* __restrict__ em, float* __restrict__ out) {
    float* sHE  = smem + OFF_HE;
    float* sEMT = smem + OFF_EMT;
    float* sUN  = smem + OFF_UN;          // x ring (phase A) / y tile (phase B)

    const int tid   = threadIdx.x;
    const int ttile = blockIdx.x;
    const int b     = blockIdx.y;
    const int t0    = ttile * TT;
    const int cl    = tid >> 3;           // 0..31
    const int t     = tid & 7;            // 0..7

    const unsigned ringBase = smem_u32(sUN);

    // ---- chunk issue: 4 x 16B cp.async per thread ----
    auto issue_chunk = [&](int ch) {
        const int buf = ch & 1;
        #pragma unroll
        for (int i = 0; i < 4; i++) {
            int idx = i * 256 + tid;          // 1024 float4 per chunk
            int n   = idx >> 7;               // 0..7
            int rem = idx & 127;
            int c   = rem >> 1;               // 0..63
            int tq  = rem & 1;                // 0..1
            const float* g = x + ((size_t)(b * Cc + c) * Nn + (size_t)ch * CHN + n) * Tt
                               + t0 + tq * 4;
            unsigned d = ringBase + (unsigned)(buf * CHUNK_FLOATS + (n * Cc + c) * TT + tq * 4) * 4u;
            cp_async16(d, g);
        }
        asm volatile("cp.async.commit_group;" ::: "memory");
    };

    // prime the ring before staging (independent smem regions)
    issue_chunk(0);
    issue_chunk(1);

    // ---- stage HEs + EM^T ----
    const float4* heg = (const float4*)HEs;
    float4* sheg = (float4*)sHE;
    #pragma unroll
    for (int i = 0; i < 16; i++)                 // 4096 float4
        sheg[i * 256 + tid] = heg[i * 256 + tid];
    #pragma unroll
    for (int i = 0; i < 4; i++) {
        int flat = i * 256 + tid;                // flat = k'*32 + j
        int kp = flat >> 5, k = flat & 31;
        sEMT[k * Kk + kp] = em[flat];            // sEMT[j][k'] = EM[k'][j]
    }
    __syncthreads();

    // =========================== Phase A: HF ================================
    u64 accA[16], accB[16];
    #pragma unroll
    for (int i = 0; i < 16; i++) { accA[i] = 0ull; accB[i] = 0ull; }

    #pragma unroll 1
    for (int ch = 0; ch < NCH; ch++) {
        if (ch >= NCH - 2) asm volatile("cp.async.wait_group 0;" ::: "memory");
        else               asm volatile("cp.async.wait_group 1;" ::: "memory");
        __syncthreads();                          // chunk ch visible to all

        const float* sX = sUN + (ch & 1) * CHUNK_FLOATS;
        #pragma unroll
        for (int i = 0; i < CHN; i++) {
            float xa = sX[(i * Cc + cl)      * TT + t];
            float xb = sX[(i * Cc + cl + 32) * TT + t];
            u64 xap = pack2(xa, xa);
            u64 xbp = pack2(xb, xb);
            const ulonglong2* he = (const ulonglong2*)(sHE + (ch * CHN + i) * Kk);
            #pragma unroll
            for (int q = 0; q < 8; q++) {         // broadcast LDS.128 -> 4 FFMA2
                ulonglong2 hh = he[q];
                accA[2 * q]     = ffma2(hh.x, xap, accA[2 * q]);
                accA[2 * q + 1] = ffma2(hh.y, xap, accA[2 * q + 1]);
                accB[2 * q]     = ffma2(hh.x, xbp, accB[2 * q]);
                accB[2 * q + 1] = ffma2(hh.y, xbp, accB[2 * q + 1]);
            }
        }
        __syncthreads();                          // done reading buf before refill
        if (ch + 2 < NCH) issue_chunk(ch + 2);
    }

    // ---- edge-map mix + HO = relu(mix)+HF, per c (sequential to save regs) ----
    // c = cl
    {
        u64 hm[16];
        #pragma unroll
        for (int i = 0; i < 16; i++) hm[i] = 0ull;
        #pragma unroll
        for (int k = 0; k < Kk; k++) {
            float2 a = unpack2(accA[k >> 1]);
            float hf = (k & 1) ? a.y : a.x;
            u64 hb = pack2(hf, hf);
            const ulonglong2* emr = (const ulonglong2*)(sEMT + k * Kk);
            #pragma unroll
            for (int q = 0; q < 8; q++) {
                ulonglong2 ee = emr[q];
                hm[2 * q]     = ffma2(ee.x, hb, hm[2 * q]);
                hm[2 * q + 1] = ffma2(ee.y, hb, hm[2 * q + 1]);
            }
        }
        #pragma unroll
        for (int kp = 0; kp < 16; kp++) {
            float2 m = unpack2(hm[kp]);
            float2 f = unpack2(accA[kp]);
            accA[kp] = pack2(fmaxf(m.x, 0.f) + f.x, fmaxf(m.y, 0.f) + f.y); // accA := hoA
        }
    }
    // c = cl + 32
    {
        u64 hm[16];
        #pragma unroll
        for (int i = 0; i < 16; i++) hm[i] = 0ull;
        #pragma unroll
        for (int k = 0; k < Kk; k++) {
            float2 a = unpack2(accB[k >> 1]);
            float hf = (k & 1) ? a.y : a.x;
            u64 hb = pack2(hf, hf);
            const ulonglong2* emr = (const ulonglong2*)(sEMT + k * Kk);
            #pragma unroll
            for (int q = 0; q < 8; q++) {
                ulonglong2 ee = emr[q];
                hm[2 * q]     = ffma2(ee.x, hb, hm[2 * q]);
                hm[2 * q + 1] = ffma2(ee.y, hb, hm[2 * q + 1]);
            }
        }
        #pragma unroll
        for (int kp = 0; kp < 16; kp++) {
            float2 m = unpack2(hm[kp]);
            float2 f = unpack2(accB[kp]);
            accB[kp] = pack2(fmaxf(m.x, 0.f) + f.x, fmaxf(m.y, 0.f) + f.y); // accB := hoB
        }
    }
    __syncthreads();   // ring reads done everywhere; sUN becomes y tile

    // =========================== Phase B ====================================
    float* sY = sUN;
    const int enl = tid >> 4;            // 0..15 local n (epilogue)
    const int et  = (tid >> 1) & 7;      // 0..7  t
    const int ech = tid & 1;             // c half
    const int cb  = ech * 32;
    const size_t cstride = (size_t)Nn * Tt;

    #pragma unroll 1
    for (int nt = 0; nt < Nn / NTILE; nt++) {
        const int n0 = nt * NTILE;

        // GEMM: y[n] = dot(HE[n,:], HO[:]) via k-pair FFMA2 + horizontal add
        #pragma unroll 4
        for (int i = 0; i < NTILE; i++) {
            const ulonglong2* he = (const ulonglong2*)(sHE + (n0 + i) * Kk);
            u64 ya = 0ull, yb = 0ull;
            #pragma unroll
            for (int q = 0; q < 8; q++) {
                ulonglong2 hh = he[q];
                ya = ffma2(hh.x, accA[2 * q], ya);
                ya = ffma2(hh.y, accA[2 * q + 1], ya);
                yb = ffma2(hh.x, accB[2 * q], yb);
                yb = ffma2(hh.y, accB[2 * q + 1], yb);
            }
            float2 a = unpack2(ya);
            float2 bb = unpack2(yb);
            sY[(i * TT + t) * YSTR + cl]      = a.x + a.y;
            sY[(i * TT + t) * YSTR + cl + 32] = bb.x + bb.y;
        }
        __syncthreads();

        // epilogue: relu + residual + LN over c (2 threads per (n,t), shfl pair)
        const int n = n0 + enl;
        const float* yrow = sY + (enl * TT + et) * YSTR + cb;
        const size_t xbase = ((size_t)(b * Cc + cb) * Nn + n) * Tt + t0 + et;

        float z[32];
        float s1 = 0.f, s2 = 0.f;
        #pragma unroll
        for (int i = 0; i < 32; i++) {
            float zz = fmaxf(yrow[i], 0.f) + x[xbase + (size_t)i * cstride];
            z[i] = zz;
            s1 += zz;
            s2 += zz * zz;
        }
        s1 += __shfl_xor_sync(0xffffffffu, s1, 1);
        s2 += __shfl_xor_sync(0xffffffffu, s2, 1);
        float mu  = s1 * (1.f / 64.f);
        float var = fmaf(mu, -mu, s2 * (1.f / 64.f));
        float inv = rsqrtf(var + 1e-5f);
        #pragma unroll
        for (int i = 0; i < 32; i++)
            out[xbase + (size_t)i * cstride] = (z[i] - mu) * inv;
        __syncthreads();
    }
}

// ============================================================================
extern "C" void kernel_launch(void* const* d_in, const int* in_sizes, int n_in,
                              void* d_out, int out_size) {
    const float* x   = (const float*)d_in[0];
    const float* HEs = (const float*)d_in[1];
    const float* em  = (const float*)d_in[2];
    float* out = (float*)d_out;

    const int smem_bytes = SMEM_FLOATS * 4;   // 103424 -> 2 CTAs/SM
    cudaFuncSetAttribute(fused_hgl, cudaFuncAttributeMaxDynamicSharedMemorySize, smem_bytes);

    fused_hgl<<<dim3(Tt / TT, Bx), 256, smem_bytes>>>(x, HEs, em, out);
}